// round 4
// baseline (speedup 1.0000x reference)
#include <cuda_runtime.h>
#include <cuda_bf16.h>

// MedianFilter1D: k=9 sliding median along last axis, replicate padding.
// x: [B, C, L] fp32, L = 8192, B*C = 2048 rows.
//
// R4 vs R3 (31.5us, occ up but issue DOWN): the barrier-phased smem design
// was the bottleneck, not occupancy. This version has NO smem and NO
// __syncthreads: each thread does 3 overlapping aligned LDG.128 (L1 serves
// the 16B-shifted overlap between lanes), computes 4 outputs (17 min/max
// ops each via the sorted-triple identity), and writes one STG.128.
// Row-edge replicate padding handled by a rare clamped scalar-load path
// (2 threads per row).

#define ROW_L 8192
#define Q_PER_ROW (ROW_L / 4)      // 2048 output-quads per row
#define NT 256

__device__ __forceinline__ void cswap(float& a, float& b) {
    float lo = fminf(a, b);
    b = fmaxf(a, b);
    a = lo;
}

__device__ __forceinline__ void sort3(float& a, float& b, float& c) {
    cswap(a, b);
    cswap(b, c);
    cswap(a, b);
}

__device__ __forceinline__ float med3(float a, float b, float c) {
    return fmaxf(fminf(a, b), fminf(fmaxf(a, b), c));   // 4 ops
}

// Insert x into sorted pair (p0 <= p1) -> sorted triple (4 ops)
__device__ __forceinline__ void insert3(float x, float p0, float p1,
                                        float& a0, float& a1, float& a2) {
    a0 = fminf(x, p0);
    float m = fmaxf(x, p0);
    a1 = fminf(m, p1);
    a2 = fmaxf(m, p1);
}

__global__ __launch_bounds__(NT, 6)
void median9_kernel(const float* __restrict__ x, float* __restrict__ y) {
    const int g   = blockIdx.x * NT + threadIdx.x;   // one output-quad per thread
    const int row = g >> 11;                         // g / Q_PER_ROW
    const int lo  = (g & (Q_PER_ROW - 1)) * 4;       // quad base within row

    const float* __restrict__ xr = x + ((size_t)row << 13);

    // Window for outputs lo..lo+3 is x[lo-4 .. lo+11] -> v0..v11.
    float v0, v1, v2, v3, v4, v5, v6, v7, v8, v9, v10, v11;

    if (lo >= 4 && lo <= ROW_L - 8) {
        // Fast path: 3 aligned float4 loads (overlap between lanes hits L1).
        const float4* p = (const float4*)(xr + lo - 4);
        float4 qa = p[0], qb = p[1], qc = p[2];
        v0 = qa.x; v1 = qa.y; v2  = qa.z; v3  = qa.w;
        v4 = qb.x; v5 = qb.y; v6  = qb.z; v7  = qb.w;
        v8 = qc.x; v9 = qc.y; v10 = qc.z; v11 = qc.w;
    } else {
        // Row-edge path (2 threads/row): elementwise clamped loads.
        float v[12];
        #pragma unroll
        for (int i = 0; i < 12; i++) {
            int idx = lo - 4 + i;
            idx = min(max(idx, 0), ROW_L - 1);
            v[i] = xr[idx];
        }
        v0 = v[0]; v1 = v[1]; v2  = v[2];  v3  = v[3];
        v4 = v[4]; v5 = v[5]; v6  = v[6];  v7  = v[7];
        v8 = v[8]; v9 = v[9]; v10 = v[10]; v11 = v[11];
    }

    // Shared middle triples T1={v3,v4,v5}, T2={v6,v7,v8}, sorted.
    float b0 = v3, b1 = v4, b2 = v5; sort3(b0, b1, b2);
    float c0 = v6, c1 = v7, c2 = v8; sort3(c0, c1, c2);

    // Hoisted reductions over the shared triples.
    const float mm = fmaxf(b0, c0);     // max of T-mins
    const float nn = fminf(b2, c2);     // min of T-maxes
    const float p  = fminf(b1, c1);     // clamp lo
    const float q  = fmaxf(b1, c1);     // clamp hi

    // Sorted pairs reused by the a-triples.
    float s1 = fminf(v1, v2),  s2 = fmaxf(v1, v2);    // (v1,v2)
    float t1 = fminf(v9, v10), t2 = fmaxf(v9, v10);   // (v9,v10)

    float4 r;
    float a0, a1, a2;

    // out lo:   {v0,v1,v2} u T1 u T2
    insert3(v0, s1, s2, a0, a1, a2);
    r.x = med3(fmaxf(a0, mm), fmaxf(p, fminf(q, a1)), fminf(a2, nn));

    // out lo+1: {v1,v2,v9} u T1 u T2
    insert3(v9, s1, s2, a0, a1, a2);
    r.y = med3(fmaxf(a0, mm), fmaxf(p, fminf(q, a1)), fminf(a2, nn));

    // out lo+2: {v2,v9,v10} u T1 u T2
    insert3(v2, t1, t2, a0, a1, a2);
    r.z = med3(fmaxf(a0, mm), fmaxf(p, fminf(q, a1)), fminf(a2, nn));

    // out lo+3: {v9,v10,v11} u T1 u T2
    insert3(v11, t1, t2, a0, a1, a2);
    r.w = med3(fmaxf(a0, mm), fmaxf(p, fminf(q, a1)), fminf(a2, nn));

    *(float4*)(y + ((size_t)row << 13) + lo) = r;
}

extern "C" void kernel_launch(void* const* d_in, const int* in_sizes, int n_in,
                              void* d_out, int out_size) {
    const float* x = (const float*)d_in[0];
    float* y = (float*)d_out;
    const int total_quads = in_sizes[0] / 4;          // 4.19M threads
    median9_kernel<<<total_quads / NT, NT>>>(x, y);
}

// round 5
// speedup vs baseline: 1.3765x; 1.3765x over previous
#include <cuda_runtime.h>
#include <cuda_bf16.h>

// MedianFilter1D: k=9 sliding median along last axis, replicate padding.
// x: [B, C, L] fp32, L = 8192. One CTA per row (B*C = 2048 rows).
//
// R5 = R2 structure (best: 21.5us kernel) with:
//  - __launch_bounds__(256,6): regs <=42 (R3 compiled this math to 38),
//    theoretical occupancy 62.5% -> 75%, attacking issue slack.
//  - qs2/qt2 fold: 66 min/max ops per 4 outputs (was 68).
//  - __stcs streaming stores (outputs never re-read; cut L1 pressure).

#define ROW_L 8192
#define PAD   4
#define NTHREADS 256
#define ITERS (ROW_L / 4 / NTHREADS)   // 8

__device__ __forceinline__ void cswap(float& a, float& b) {
    float lo = fminf(a, b);
    b = fmaxf(a, b);
    a = lo;
}

__device__ __forceinline__ void sort3(float& a, float& b, float& c) {
    cswap(a, b);
    cswap(b, c);
    cswap(a, b);
}

__device__ __forceinline__ float med3(float a, float b, float c) {
    return fmaxf(fminf(a, b), fminf(fmaxf(a, b), c));   // 4 ops
}

// One output: insert x into sorted pair (p0<=p1), combine with hoisted
// shared-triple reductions (mm, nn, p, qp1 = min(q,p1)).  11 ops.
__device__ __forceinline__ float median_out(float x, float p0, float p1,
                                            float mm, float nn,
                                            float p, float qp1) {
    float a0 = fminf(x, p0);
    float m  = fmaxf(x, p0);
    float lo  = fmaxf(a0, mm);
    float mid = fmaxf(p, fminf(qp1, m));          // = max(p, min(q, min(m,p1)))
    float hi  = fminf(fmaxf(m, p1), nn);
    return med3(lo, mid, hi);
}

__global__ __launch_bounds__(NTHREADS, 6)
void median9_kernel(const float* __restrict__ x, float* __restrict__ y) {
    __shared__ __align__(16) float s[ROW_L + 2 * PAD];

    const int row = blockIdx.x;
    const float* xr = x + (size_t)row * ROW_L;
    float* yr       = y + (size_t)row * ROW_L;
    const int t = threadIdx.x;

    // ---- Stage row into smem (float4, coalesced). s[PAD + i] = xr[i]. ----
    const float4* x4 = (const float4*)xr;
    #pragma unroll
    for (int j = 0; j < ITERS; j++) {
        int i = t + NTHREADS * j;
        float4 v = x4[i];
        *(float4*)&s[PAD + 4 * i] = v;
        if (j == 0 && t == 0) {                      // left replicate halo
            s[0] = v.x; s[1] = v.x; s[2] = v.x; s[3] = v.x;
        }
        if (j == ITERS - 1 && t == NTHREADS - 1) {   // right replicate halo
            s[ROW_L + PAD + 0] = v.w;
            s[ROW_L + PAD + 1] = v.w;
            s[ROW_L + PAD + 2] = v.w;
            s[ROW_L + PAD + 3] = v.w;
        }
    }
    __syncthreads();

    // ---- 4 consecutive outputs per iteration from 12 values. ----
    // Output p uses window s[p .. p+8] (padded-array indexing).
    #pragma unroll
    for (int j = 0; j < ITERS; j++) {
        const int o = 4 * t + 4 * NTHREADS * j;      // output base (mult of 4)

        float4 va = *(const float4*)&s[o];           // v0..v3
        float4 vb = *(const float4*)&s[o + 4];       // v4..v7
        float4 vc = *(const float4*)&s[o + 8];       // v8..v11

        // Shared middle triples T1={v3,v4,v5}, T2={v6,v7,v8}, sorted.
        float b0 = va.w, b1 = vb.x, b2 = vb.y; sort3(b0, b1, b2);   // 6
        float c0 = vb.z, c1 = vb.w, c2 = vc.x; sort3(c0, c1, c2);   // 6

        // Hoisted reductions over the shared triples.
        const float mm = fmaxf(b0, c0);              // max of T-mins
        const float nn = fminf(b2, c2);              // min of T-maxes
        const float p  = fminf(b1, c1);              // clamp lo
        const float q  = fmaxf(b1, c1);              // clamp hi

        // Sorted pairs reused by the a-triples, + folded clamp bound.
        float s1 = fminf(va.y, va.z), s2 = fmaxf(va.y, va.z);  // (v1,v2)
        float t1 = fminf(vc.y, vc.z), t2 = fmaxf(vc.y, vc.z);  // (v9,v10)
        const float qs2 = fminf(q, s2);
        const float qt2 = fminf(q, t2);

        float4 r;
        r.x = median_out(va.x, s1, s2, mm, nn, p, qs2);  // {v0,v1,v2}  u T1 u T2
        r.y = median_out(vc.y, s1, s2, mm, nn, p, qs2);  // {v1,v2,v9}  u T1 u T2
        r.z = median_out(va.z, t1, t2, mm, nn, p, qt2);  // {v2,v9,v10} u T1 u T2
        r.w = median_out(vc.w, t1, t2, mm, nn, p, qt2);  // {v9,v10,v11}u T1 u T2

        __stcs((float4*)(yr + o), r);                // streaming store
    }
}

extern "C" void kernel_launch(void* const* d_in, const int* in_sizes, int n_in,
                              void* d_out, int out_size) {
    const float* x = (const float*)d_in[0];
    float* y = (float*)d_out;
    const int rows = in_sizes[0] / ROW_L;            // B*C = 2048
    median9_kernel<<<rows, NTHREADS>>>(x, y);
}